// round 4
// baseline (speedup 1.0000x reference)
#include <cuda_runtime.h>
#include <cuda_bf16.h>

// Problem constants
#define T_DIM 8
#define C_DIM 3
#define HW    65536   // 256*256
#define NPIX  262144  // B(4) * HW

// ---------------- packed f32x2 helpers (Blackwell) ----------------
typedef unsigned long long f32x2;

__device__ __forceinline__ f32x2 pack2(float lo, float hi) {
    f32x2 r; asm("mov.b64 %0, {%1, %2};" : "=l"(r) : "f"(lo), "f"(hi)); return r;
}
__device__ __forceinline__ void unpack2(f32x2 v, float& lo, float& hi) {
    asm("mov.b64 {%0, %1}, %2;" : "=f"(lo), "=f"(hi) : "l"(v));
}
__device__ __forceinline__ f32x2 fma2(f32x2 a, f32x2 b, f32x2 c) {
    f32x2 d; asm("fma.rn.f32x2 %0, %1, %2, %3;" : "=l"(d) : "l"(a), "l"(b), "l"(c)); return d;
}
__device__ __forceinline__ f32x2 add2(f32x2 a, f32x2 b) {
    f32x2 d; asm("add.rn.f32x2 %0, %1, %2;" : "=l"(d) : "l"(a), "l"(b)); return d;
}
__device__ __forceinline__ f32x2 mul2(f32x2 a, f32x2 b) {
    f32x2 d; asm("mul.rn.f32x2 %0, %1, %2;" : "=l"(d) : "l"(a), "l"(b)); return d;
}
__device__ __forceinline__ f32x2 ex2_2(f32x2 v) {
    float lo, hi; unpack2(v, lo, hi);
    float el, eh;
    asm("ex2.approx.ftz.f32 %0, %1;" : "=f"(el) : "f"(lo));
    asm("ex2.approx.ftz.f32 %0, %1;" : "=f"(eh) : "f"(hi));
    return pack2(el, eh);
}
__device__ __forceinline__ f32x2 rcp_2(f32x2 v) {
    float lo, hi; unpack2(v, lo, hi);
    float rl, rh;
    asm("rcp.approx.ftz.f32 %0, %1;" : "=f"(rl) : "f"(lo));
    asm("rcp.approx.ftz.f32 %0, %1;" : "=f"(rh) : "f"(hi));
    return pack2(rl, rh);
}

// Fused kernel: each block folds the weights into 103 constants (shared),
// then processes 256 threads x 2 pixels with packed f32x2 math.
//
// Folded constants (score path pre-scaled by 1/sqrt(8)*log2(e) for raw ex2):
//   per head n (25): MT[3][3], u[3], g[3], c, P[3][3]
//   [100..102] output bias p (all value-path biases folded, weights sum to 1)
__global__ void __launch_bounds__(256, 4)
fused_kernel(const float* __restrict__ z, float* __restrict__ out,
             const float* __restrict__ W_in, const float* __restrict__ b_in,
             const float* __restrict__ W_q,  const float* __restrict__ b_q,
             const float* __restrict__ W_k,  const float* __restrict__ b_k,
             const float* __restrict__ W_v,  const float* __restrict__ b_v,
             const float* __restrict__ W_o,  const float* __restrict__ b_o) {
    __shared__ float A[32][3], Bm[32][3], Cm[32][3];
    __shared__ float aQ[32], bK[32], cV[32];
    __shared__ f32x2 cst[103];

    int tid = threadIdx.x;  // 256 threads

    // ---- setup phase 1: A = W_q@W_in etc. (384 tasks) ----
    for (int task = tid; task < 384; task += 256) {
        int m = task >> 7;
        int r = task & 127;
        const float* Wm = (m == 0) ? W_q : (m == 1) ? W_k : W_v;
        const float* bm = (m == 0) ? b_q : (m == 1) ? b_k : b_v;
        if (r < 96) {
            int o = r / 3, i = r - 3 * o;
            float s = 0.f;
            #pragma unroll
            for (int j = 0; j < 32; j++) s += Wm[o * 32 + j] * W_in[j * 3 + i];
            if (m == 0) A[o][i] = s; else if (m == 1) Bm[o][i] = s; else Cm[o][i] = s;
        } else {
            int o = r - 96;
            float s = bm[o];
            #pragma unroll
            for (int j = 0; j < 32; j++) s += Wm[o * 32 + j] * b_in[j];
            if (m == 0) aQ[o] = s; else if (m == 1) bK[o] = s; else cV[o] = s;
        }
    }
    __syncthreads();

    // ---- setup phase 2: fold into 103 constants ----
    const float scale = 0.3535533905932738f * 1.4426950408889634f;  // 1/sqrt(8)*log2(e)
    if (tid < 103) {
        float s = 0.f;
        if (tid >= 100) {
            int o = tid - 100;
            s = b_o[o];
            #pragma unroll
            for (int r = 0; r < 32; r++) s += W_o[o * 32 + r] * cV[r];
        } else {
            int n = tid / 25, k = tid - 25 * n;
            int base = n * 8;
            if (k < 9) {
                int j = k / 3, i = k - 3 * j;
                #pragma unroll
                for (int d = 0; d < 8; d++) s += A[base + d][i] * Bm[base + d][j];
                s *= scale;
            } else if (k < 12) {
                int j = k - 9;
                #pragma unroll
                for (int d = 0; d < 8; d++) s += aQ[base + d] * Bm[base + d][j];
                s *= scale;
            } else if (k < 15) {
                int i = k - 12;
                #pragma unroll
                for (int d = 0; d < 8; d++) s += A[base + d][i] * bK[base + d];
                s *= scale;
            } else if (k == 15) {
                #pragma unroll
                for (int d = 0; d < 8; d++) s += aQ[base + d] * bK[base + d];
                s *= scale;
            } else {
                int kk = k - 16;
                int o = kk / 3, i = kk - 3 * o;
                #pragma unroll
                for (int d = 0; d < 8; d++) s += W_o[o * 32 + base + d] * Cm[base + d][i];
            }
        }
        cst[tid] = pack2(s, s);
    }
    __syncthreads();

    // ---- main phase: 2 pixels per thread, packed f32x2 ----
    int gid = blockIdx.x * 256 + tid;       // 131072 threads
    int pix = gid << 1;
    int b  = pix >> 16;
    int hw = pix & (HW - 1);

    const float* zp = z + (size_t)b * (T_DIM * C_DIM * HW) + hw;

    // z7 first: r/s computation depends only on it, overlaps remaining loads
    f32x2 z70 = *reinterpret_cast<const f32x2*>(zp + (size_t)21 * HW);
    f32x2 z71 = *reinterpret_cast<const f32x2*>(zp + (size_t)22 * HW);
    f32x2 z72 = *reinterpret_cast<const f32x2*>(zp + (size_t)23 * HW);

    f32x2 zv[21];                           // t=0..6 planes
    #pragma unroll
    for (int i = 0; i < 21; i++)
        zv[i] = *reinterpret_cast<const f32x2*>(zp + (size_t)i * HW);

    f32x2 o0 = cst[100], o1 = cst[101], o2 = cst[102];

    #pragma unroll
    for (int n = 0; n < 4; n++) {
        const f32x2* cs = cst + n * 25;
        f32x2 r0 = fma2(cs[0], z70, fma2(cs[1], z71, fma2(cs[2], z72, cs[9])));
        f32x2 r1 = fma2(cs[3], z70, fma2(cs[4], z71, fma2(cs[5], z72, cs[10])));
        f32x2 r2 = fma2(cs[6], z70, fma2(cs[7], z71, fma2(cs[8], z72, cs[11])));
        f32x2 s  = fma2(cs[12], z70, fma2(cs[13], z71, fma2(cs[14], z72, cs[15])));

        f32x2 esum = 0ULL, zb0 = 0ULL, zb1 = 0ULL, zb2 = 0ULL;
        #pragma unroll
        for (int t = 0; t < T_DIM; t++) {
            f32x2 a0 = (t < 7) ? zv[t * 3]     : z70;
            f32x2 a1 = (t < 7) ? zv[t * 3 + 1] : z71;
            f32x2 a2 = (t < 7) ? zv[t * 3 + 2] : z72;
            f32x2 sc = fma2(r0, a0, fma2(r1, a1, fma2(r2, a2, s)));
            f32x2 e  = ex2_2(sc);   // scores tiny: no max-subtraction needed
            esum = add2(esum, e);
            zb0 = fma2(e, a0, zb0);
            zb1 = fma2(e, a1, zb1);
            zb2 = fma2(e, a2, zb2);
        }
        f32x2 inv = rcp_2(esum);
        zb0 = mul2(zb0, inv); zb1 = mul2(zb1, inv); zb2 = mul2(zb2, inv);
        o0 = fma2(cs[16], zb0, fma2(cs[17], zb1, fma2(cs[18], zb2, o0)));
        o1 = fma2(cs[19], zb0, fma2(cs[20], zb1, fma2(cs[21], zb2, o1)));
        o2 = fma2(cs[22], zb0, fma2(cs[23], zb1, fma2(cs[24], zb2, o2)));
    }

    float* op = out + (size_t)b * (3 * HW) + hw;
    *reinterpret_cast<f32x2*>(op)          = o0;
    *reinterpret_cast<f32x2*>(op + HW)     = o1;
    *reinterpret_cast<f32x2*>(op + 2 * HW) = o2;
}

extern "C" void kernel_launch(void* const* d_in, const int* in_sizes, int n_in,
                              void* d_out, int out_size) {
    const float* z    = (const float*)d_in[0];
    const float* W_in = (const float*)d_in[1];
    const float* b_in = (const float*)d_in[2];
    const float* W_q  = (const float*)d_in[3];
    const float* b_q  = (const float*)d_in[4];
    const float* W_k  = (const float*)d_in[5];
    const float* b_k  = (const float*)d_in[6];
    const float* W_v  = (const float*)d_in[7];
    const float* b_v  = (const float*)d_in[8];
    const float* W_o  = (const float*)d_in[9];
    const float* b_o  = (const float*)d_in[10];
    float* out = (float*)d_out;

    fused_kernel<<<NPIX / 512, 256>>>(z, out,
                                      W_in, b_in, W_q, b_q, W_k, b_k,
                                      W_v, b_v, W_o, b_o);
}